// round 12
// baseline (speedup 1.0000x reference)
#include <cuda_runtime.h>
#include <math.h>

// Problem constants
#define B 32
#define S 2048
#define D 1024
#define MASK_PENALTY 100000000.0f

// Tiling
#define NSPLIT 16
#define WARPS 8
#define THREADS (WARPS * 32)                    // 256
#define ROWS_PER_SPLIT (S / NSPLIT)             // 128

// Scratch (allocation-free: __device__ globals, zero-init)
__device__ float g_m[B * NSPLIT];
__device__ float g_l[B * NSPLIT];
__device__ __align__(16) float g_acc[(size_t)B * NSPLIT * D];  // 2 MB
__device__ int g_cnt[B];  // zero-init; self-resets each launch

// ---------------------------------------------------------------------------
// TWO-PHASE fused attention (scores -> block softmax -> weighted sum).
// Masked rows contribute exp(-1e8)==0.0f exactly in fp32 -> skipped
// (compacted valid-row list, deterministic ballot/popc).
// Phase A: warp-per-row DOT ONLY (no accumulator state; loads front-batch;
//          2 rows interleaved per iteration) -> scores in smem.
// Softmax: one block reduction -> final M, per-row weights, L. No online
//          rescaling anywhere.
// Phase B: acc += wgt*c, weights known -> pure stream; rows are L2-resident
//          from Phase A, so this pass runs at L2 bandwidth, not DRAM.
// 8 warp partials merge in smem -> 1 per CTA -> last CTA per batch merges.
// ---------------------------------------------------------------------------
__global__ void __launch_bounds__(THREADS)
attn_fused(const float* __restrict__ target,
           const float* __restrict__ context,
           const float* __restrict__ mask,
           float* __restrict__ out)
{
    const int b     = blockIdx.x;
    const int split = blockIdx.y;
    const int w     = threadIdx.x >> 5;
    const int lane  = threadIdx.x & 31;
    const int s0    = split * ROWS_PER_SPLIT;

    __shared__ short slist[ROWS_PER_SPLIT];   // compacted valid row indices
    __shared__ int   swcnt[4];
    __shared__ int   scnt;
    __shared__ float sscore[ROWS_PER_SPLIT];  // scores by list position
    __shared__ float swgt[ROWS_PER_SPLIT];    // final softmax weights
    __shared__ float sred[WARPS];
    __shared__ __align__(16) float4 sacc[WARPS][D / 4];   // 32 KB

    // ---- Deterministic compaction of valid rows (warps 0-3) ----
    if (threadIdx.x < ROWS_PER_SPLIT) {
        const bool v = mask[(size_t)b * S + s0 + threadIdx.x] != 0.f;
        const unsigned bal = __ballot_sync(0xffffffffu, v);
        if (lane == 0) swcnt[w] = __popc(bal);
        __syncwarp();
        __syncthreads();
        int off = 0;
#pragma unroll
        for (int i = 0; i < 4; i++) off += (i < w) ? swcnt[i] : 0;
        if (threadIdx.x == 0) scnt = swcnt[0] + swcnt[1] + swcnt[2] + swcnt[3];
        if (v) {
            const int pos = off + __popc(bal & ((1u << lane) - 1u));
            slist[pos] = (short)threadIdx.x;
        }
    } else {
        __syncthreads();   // match the barrier above
    }

    // Lane's slice of the query vector (registers)
    const float4* tg = (const float4*)(target + (size_t)b * D);
    float4 t[8];
#pragma unroll
    for (int i = 0; i < 8; i++) t[i] = tg[lane + 32 * i];

    __syncthreads();
    const int cnt = scnt;
    const float* cb = context + (size_t)b * S * D;

    // ================= Phase A: scores only (2 rows/iteration) =============
    for (int p = w; p < cnt; p += 2 * WARPS) {
        const int p2 = p + WARPS;
        const bool has2 = (p2 < cnt);
        const int r1 = slist[p];
        const int r2 = slist[has2 ? p2 : p];
        const float4* row1 = (const float4*)(cb + (size_t)(s0 + r1) * D);
        const float4* row2 = (const float4*)(cb + (size_t)(s0 + r2) * D);

        float4 c1[8], c2[8];
#pragma unroll
        for (int i = 0; i < 8; i++) c1[i] = row1[lane + 32 * i];
#pragma unroll
        for (int i = 0; i < 8; i++) c2[i] = row2[lane + 32 * i];

        float a0 = 0.f, a1 = 0.f, b0 = 0.f, b1 = 0.f;
#pragma unroll
        for (int i = 0; i < 8; i++) {
            a0 = fmaf(c1[i].x, t[i].x, a0);
            a1 = fmaf(c1[i].y, t[i].y, a1);
            a0 = fmaf(c1[i].z, t[i].z, a0);
            a1 = fmaf(c1[i].w, t[i].w, a1);
            b0 = fmaf(c2[i].x, t[i].x, b0);
            b1 = fmaf(c2[i].y, t[i].y, b1);
            b0 = fmaf(c2[i].z, t[i].z, b0);
            b1 = fmaf(c2[i].w, t[i].w, b1);
        }
        float dot1 = a0 + a1;
        float dot2 = b0 + b1;
#pragma unroll
        for (int off = 16; off > 0; off >>= 1) {
            dot1 += __shfl_xor_sync(0xffffffffu, dot1, off);
            dot2 += __shfl_xor_sync(0xffffffffu, dot2, off);
        }
        if (lane == 0) {
            sscore[p] = dot1;
            if (has2) sscore[p2] = dot2;
        }
    }
    __syncthreads();

    // ============ Block softmax: M, per-row weights, L (in smem) ===========
    const float s = (threadIdx.x < cnt) ? sscore[threadIdx.x] : -INFINITY;
    float smax = s;
#pragma unroll
    for (int off = 16; off > 0; off >>= 1)
        smax = fmaxf(smax, __shfl_xor_sync(0xffffffffu, smax, off));
    if (lane == 0) sred[w] = smax;
    __syncthreads();
    float M = sred[0];
#pragma unroll
    for (int i = 1; i < WARPS; i++) M = fmaxf(M, sred[i]);

    float wg = 0.f;
    if (threadIdx.x < cnt) {
        wg = __expf(s - M);
        swgt[threadIdx.x] = wg;
    }
    float wsum = wg;
#pragma unroll
    for (int off = 16; off > 0; off >>= 1)
        wsum += __shfl_xor_sync(0xffffffffu, wsum, off);
    __syncthreads();   // everyone done reading sred for M
    if (lane == 0) sred[w] = wsum;
    __syncthreads();   // also makes swgt visible to all warps
    float L = 0.f;
#pragma unroll
    for (int i = 0; i < WARPS; i++) L += sred[i];

    // ============ Phase B: weighted accumulation (L2-resident rows) ========
    float4 acc[8];
#pragma unroll
    for (int i = 0; i < 8; i++) acc[i] = make_float4(0.f, 0.f, 0.f, 0.f);

    for (int p = w; p < cnt; p += WARPS) {
        const int r = slist[p];
        const float wgt = swgt[p];
        const float4* row = (const float4*)(cb + (size_t)(s0 + r) * D);
        float4 c[8];
#pragma unroll
        for (int i = 0; i < 8; i++) c[i] = row[lane + 32 * i];
#pragma unroll
        for (int i = 0; i < 8; i++) {
            acc[i].x = fmaf(wgt, c[i].x, acc[i].x);
            acc[i].y = fmaf(wgt, c[i].y, acc[i].y);
            acc[i].z = fmaf(wgt, c[i].z, acc[i].z);
            acc[i].w = fmaf(wgt, c[i].w, acc[i].w);
        }
    }

    // ---- In-CTA merge of the 8 warp partials (common M; plain sum) ----
#pragma unroll
    for (int i = 0; i < 8; i++) sacc[w][lane + 32 * i] = acc[i];
    __syncthreads();

    const int pidx = b * NSPLIT + split;
    const int d4 = threadIdx.x;
    float4 sum = sacc[0][d4];
#pragma unroll
    for (int i = 1; i < WARPS; i++) {
        const float4 v = sacc[i][d4];
        sum.x += v.x; sum.y += v.y; sum.z += v.z; sum.w += v.w;
    }
    ((float4*)(g_acc + (size_t)pidx * D))[d4] = sum;

    if (threadIdx.x == 0) {
        g_m[pidx] = M;   // -inf if the whole split is masked
        g_l[pidx] = L;
    }

    // ---- Last CTA per batch merges the NSPLIT partials ----
    __threadfence();
    __syncthreads();
    __shared__ int isLast;
    if (threadIdx.x == 0)
        isLast = (atomicAdd(&g_cnt[b], 1) == NSPLIT - 1);
    __syncthreads();
    if (!isLast) return;
    __threadfence();  // acquire

    float pm[NSPLIT], pl[NSPLIT];
#pragma unroll
    for (int p = 0; p < NSPLIT; p++) {
        pm[p] = __ldcg(&g_m[b * NSPLIT + p]);
        pl[p] = __ldcg(&g_l[b * NSPLIT + p]);
    }
    // Mfin is finite: position 0 of every batch is guaranteed valid.
    float Mfin = -INFINITY;
#pragma unroll
    for (int p = 0; p < NSPLIT; p++) Mfin = fmaxf(Mfin, pm[p]);
    float Lfin = 0.f;
#pragma unroll
    for (int p = 0; p < NSPLIT; p++)
        Lfin += (pm[p] > -INFINITY ? __expf(pm[p] - Mfin) : 0.f) * pl[p];
    const float Linv = 1.f / Lfin;

    float4 a = make_float4(0.f, 0.f, 0.f, 0.f);
#pragma unroll
    for (int p = 0; p < NSPLIT; p++) {
        const float fp = (pm[p] > -INFINITY) ? __expf(pm[p] - Mfin) : 0.f;
        const float4 v =
            __ldcg((const float4*)(g_acc + (size_t)(b * NSPLIT + p) * D) + d4);
        a.x = fmaf(fp, v.x, a.x);
        a.y = fmaf(fp, v.y, a.y);
        a.z = fmaf(fp, v.z, a.z);
        a.w = fmaf(fp, v.w, a.w);
    }
    a.x *= Linv; a.y *= Linv; a.z *= Linv; a.w *= Linv;
    ((float4*)(out + (size_t)b * D))[d4] = a;

    if (threadIdx.x == 0) atomicExch(&g_cnt[b], 0);
}

extern "C" void kernel_launch(void* const* d_in, const int* in_sizes, int n_in,
                              void* d_out, int out_size)
{
    const float* target  = (const float*)d_in[0];  // [B, D]
    const float* context = (const float*)d_in[1];  // [B, S, D]
    const float* mask    = (const float*)d_in[2];  // [B, S]
    float* out = (float*)d_out;                    // [B, D]

    dim3 grid(B, NSPLIT);
    attn_fused<<<grid, THREADS>>>(target, context, mask, out);
}

// round 13
// speedup vs baseline: 1.5404x; 1.5404x over previous
#include <cuda_runtime.h>
#include <math.h>

// Problem constants
#define B 32
#define S 2048
#define D 1024
#define MASK_PENALTY 100000000.0f

// Tiling
#define NSPLIT 16
#define WARPS 8
#define THREADS (WARPS * 32)                    // 256
#define ROWS_PER_SPLIT (S / NSPLIT)             // 128
#define NSLOTS 3                                // per-warp smem ring depth
#define ROW_BYTES (D * 4)                       // 4096

#define SLOTS_BYTES (WARPS * NSLOTS * ROW_BYTES)   // 96 KB dynamic smem

// Scratch (allocation-free: __device__ globals, zero-init)
__device__ float g_m[B * NSPLIT];
__device__ float g_l[B * NSPLIT];
__device__ __align__(16) float g_acc[(size_t)B * NSPLIT * D];  // 2 MB
__device__ int g_cnt[B];  // zero-init; self-resets each launch

// ---- mbarrier / bulk-copy helpers ----
__device__ __forceinline__ unsigned smem_u32(const void* p) {
    return (unsigned)__cvta_generic_to_shared(p);
}
__device__ __forceinline__ void mbar_init(unsigned mbar, unsigned count) {
    asm volatile("mbarrier.init.shared.b64 [%0], %1;" :: "r"(mbar), "r"(count)
                 : "memory");
}
__device__ __forceinline__ void mbar_expect_tx(unsigned mbar, unsigned bytes) {
    asm volatile("mbarrier.arrive.expect_tx.shared.b64 _, [%0], %1;"
                 :: "r"(mbar), "r"(bytes) : "memory");
}
__device__ __forceinline__ void mbar_wait(unsigned mbar, unsigned phase) {
    asm volatile(
        "{\n\t.reg .pred P;\n\t"
        "WL_%=:\n\t"
        "mbarrier.try_wait.parity.acquire.cta.shared::cta.b64 P, [%0], %1, 0x989680;\n\t"
        "@!P bra WL_%=;\n\t"
        "}" :: "r"(mbar), "r"(phase) : "memory");
}
__device__ __forceinline__ void bulk_cp_4k(unsigned dst, const void* src,
                                           unsigned mbar) {
    asm volatile(
        "cp.async.bulk.shared::cluster.global.mbarrier::complete_tx::bytes "
        "[%0], [%1], %2, [%3];"
        :: "r"(dst), "l"(src), "r"((unsigned)ROW_BYTES), "r"(mbar) : "memory");
}

// ---------------------------------------------------------------------------
// Fused single-pass online-softmax attention: mask skipping + compaction +
// per-warp cp.async.bulk (UBLKCP) smem ring.
// Masked rows contribute exp(-1e8)==0.0f exactly in fp32 -> skipped.
// Each warp owns a 3-slot x 4KB smem ring + 3 mbarriers. Lane 0 issues ONE
// bulk-copy instruction per row (engine-driven HBM->SMEM, zero registers,
// zero scoreboard coupling), keeping 2-3 rows in flight through the warp's
// serial reduce/exp windows. Compute reads rows from smem.
// 8 warp partials merge in smem (ring reused) -> 1 per CTA -> last CTA per
// batch merges the NSPLIT split partials (no second kernel).
// ---------------------------------------------------------------------------
__global__ void __launch_bounds__(THREADS)
attn_fused(const float* __restrict__ target,
           const float* __restrict__ context,
           const float* __restrict__ mask,
           float* __restrict__ out)
{
    extern __shared__ __align__(128) char slots[];   // [WARPS][NSLOTS][4096]

    const int b     = blockIdx.x;
    const int split = blockIdx.y;
    const int w     = threadIdx.x >> 5;
    const int lane  = threadIdx.x & 31;
    const int s0    = split * ROWS_PER_SPLIT;

    __shared__ __align__(8) unsigned long long mbar_s[WARPS][NSLOTS];
    __shared__ short slist[ROWS_PER_SPLIT];
    __shared__ int   swcnt[4];
    __shared__ int   scnt;
    __shared__ float sm_[WARPS];
    __shared__ float sl_[WARPS];

    // ---- Barrier init + deterministic compaction of valid rows ----
    if (threadIdx.x < WARPS * NSLOTS)
        mbar_init(smem_u32(&mbar_s[threadIdx.x / NSLOTS][threadIdx.x % NSLOTS]), 1);

    const bool v = (threadIdx.x < ROWS_PER_SPLIT) &&
                   (mask[(size_t)b * S + s0 + threadIdx.x] != 0.f);
    const unsigned bal = __ballot_sync(0xffffffffu, v);
    if (lane == 0 && w < 4) swcnt[w] = __popc(bal);
    __syncthreads();

    if (threadIdx.x == 0) scnt = swcnt[0] + swcnt[1] + swcnt[2] + swcnt[3];
    if (v) {
        int off = 0;
#pragma unroll
        for (int i = 0; i < 4; i++) off += (i < w) ? swcnt[i] : 0;
        const int pos = off + __popc(bal & ((1u << lane) - 1u));
        slist[pos] = (short)threadIdx.x;
    }

    // Lane's slice of the query vector (registers)
    const float4* tg = (const float4*)(target + (size_t)b * D);
    float4 t[8];
#pragma unroll
    for (int i = 0; i < 8; i++) t[i] = tg[lane + 32 * i];

    __syncthreads();
    const int cnt = scnt;
    const float* cb = context + (size_t)b * S * D;

    // This warp's ring
    char* wslot = slots + (size_t)w * NSLOTS * ROW_BYTES;
    const unsigned slot_u32 = smem_u32(wslot);
    unsigned mb[NSLOTS];
#pragma unroll
    for (int k = 0; k < NSLOTS; k++) mb[k] = smem_u32(&mbar_s[w][k]);

    // Prologue: lane 0 issues bulk copies for the first NSLOTS rows
    if (lane == 0) {
#pragma unroll
        for (int k = 0; k < NSLOTS; k++) {
            const int p = w + k * WARPS;
            if (p < cnt) {
                mbar_expect_tx(mb[k], ROW_BYTES);
                bulk_cp_4k(slot_u32 + k * ROW_BYTES,
                           cb + (size_t)(s0 + slist[p]) * D, mb[k]);
            }
        }
    }

    float4 acc[8];
#pragma unroll
    for (int i = 0; i < 8; i++) acc[i] = make_float4(0.f, 0.f, 0.f, 0.f);

    float m = -INFINITY;
    float l = 0.f;

    // ---- Mainloop: consume rows from the smem ring ----
    for (int i = 0; w + i * WARPS < cnt; i++) {
        const int slot  = i % NSLOTS;
        const unsigned phase = (unsigned)((i / NSLOTS) & 1);

        mbar_wait(mb[slot], phase);

        const float4* sp = (const float4*)(wslot + slot * ROW_BYTES);
        float4 c[8];
#pragma unroll
        for (int j = 0; j < 8; j++) c[j] = sp[lane + 32 * j];

        // Refill this slot with the row NSLOTS iterations ahead.
        // (LDS above are issued before this in the warp's stream; bulk writes
        //  land >>100 cycles later, long after the 29-cycle LDS returns.)
        const int pn = w + (i + NSLOTS) * WARPS;
        if (lane == 0 && pn < cnt) {
            mbar_expect_tx(mb[slot], ROW_BYTES);
            bulk_cp_4k(slot_u32 + slot * ROW_BYTES,
                       cb + (size_t)(s0 + slist[pn]) * D, mb[slot]);
        }

        // dot(context_row, target) for this lane's slice (2 chains)
        float d0 = 0.f, d1 = 0.f;
#pragma unroll
        for (int j = 0; j < 8; j++) {
            d0 = fmaf(c[j].x, t[j].x, d0);
            d1 = fmaf(c[j].y, t[j].y, d1);
            d0 = fmaf(c[j].z, t[j].z, d0);
            d1 = fmaf(c[j].w, t[j].w, d1);
        }
        float dot = d0 + d1;
#pragma unroll
        for (int off = 16; off > 0; off >>= 1)
            dot += __shfl_xor_sync(0xffffffffu, dot, off);

        // online softmax update (valid row => mask penalty term is 0)
        const float mnew  = fmaxf(m, dot);
        const float scale = __expf(m - mnew);     // 0 on first valid row
        const float wgt   = __expf(dot - mnew);
        l = l * scale + wgt;
#pragma unroll
        for (int j = 0; j < 8; j++) {
            acc[j].x = fmaf(acc[j].x, scale, wgt * c[j].x);
            acc[j].y = fmaf(acc[j].y, scale, wgt * c[j].y);
            acc[j].z = fmaf(acc[j].z, scale, wgt * c[j].z);
            acc[j].w = fmaf(acc[j].w, scale, wgt * c[j].w);
        }
        m = mnew;
    }

    // ---- In-CTA merge of the 8 warp partials (ring memory reused) ----
    if (lane == 0) { sm_[w] = m; sl_[w] = l; }
    __syncthreads();   // all warps done with their ring slots

    float Mcta = -INFINITY;
#pragma unroll
    for (int i = 0; i < WARPS; i++) Mcta = fmaxf(Mcta, sm_[i]);

    float4* sacc = (float4*)slots;   // [WARPS][D/4] = 32 KB within 96 KB
    const float f = (m > -INFINITY) ? __expf(m - Mcta) : 0.f;
#pragma unroll
    for (int i = 0; i < 8; i++) {
        float4 a = acc[i];
        a.x *= f; a.y *= f; a.z *= f; a.w *= f;
        sacc[w * (D / 4) + lane + 32 * i] = a;
    }
    __syncthreads();

    // 256 threads sum across the 8 warps, write CTA partial
    const int pidx = b * NSPLIT + split;
    const int d4 = threadIdx.x;
    float4 sum = sacc[d4];
#pragma unroll
    for (int i = 1; i < WARPS; i++) {
        const float4 vv = sacc[i * (D / 4) + d4];
        sum.x += vv.x; sum.y += vv.y; sum.z += vv.z; sum.w += vv.w;
    }
    ((float4*)(g_acc + (size_t)pidx * D))[d4] = sum;

    if (threadIdx.x == 0) {
        float L = 0.f;
#pragma unroll
        for (int i = 0; i < WARPS; i++)
            L += (sm_[i] > -INFINITY ? __expf(sm_[i] - Mcta) : 0.f) * sl_[i];
        g_m[pidx] = Mcta;   // -inf if the whole split is masked
        g_l[pidx] = L;
    }

    // ---- Last CTA per batch merges the NSPLIT partials ----
    __threadfence();
    __syncthreads();
    __shared__ int isLast;
    if (threadIdx.x == 0)
        isLast = (atomicAdd(&g_cnt[b], 1) == NSPLIT - 1);
    __syncthreads();
    if (!isLast) return;
    __threadfence();  // acquire

    float pm[NSPLIT], pl[NSPLIT];
#pragma unroll
    for (int p = 0; p < NSPLIT; p++) {
        pm[p] = __ldcg(&g_m[b * NSPLIT + p]);
        pl[p] = __ldcg(&g_l[b * NSPLIT + p]);
    }
    // M is finite: position 0 of every batch is guaranteed valid.
    float M = -INFINITY;
#pragma unroll
    for (int p = 0; p < NSPLIT; p++) M = fmaxf(M, pm[p]);
    float L = 0.f;
#pragma unroll
    for (int p = 0; p < NSPLIT; p++)
        L += (pm[p] > -INFINITY ? __expf(pm[p] - M) : 0.f) * pl[p];
    const float Linv = 1.f / L;

    float4 a = make_float4(0.f, 0.f, 0.f, 0.f);
#pragma unroll
    for (int p = 0; p < NSPLIT; p++) {
        const float fp = (pm[p] > -INFINITY) ? __expf(pm[p] - M) : 0.f;
        const float4 vv =
            __ldcg((const float4*)(g_acc + (size_t)(b * NSPLIT + p) * D) + d4);
        a.x = fmaf(fp, vv.x, a.x);
        a.y = fmaf(fp, vv.y, a.y);
        a.z = fmaf(fp, vv.z, a.z);
        a.w = fmaf(fp, vv.w, a.w);
    }
    a.x *= Linv; a.y *= Linv; a.z *= Linv; a.w *= Linv;
    ((float4*)(out + (size_t)b * D))[d4] = a;

    if (threadIdx.x == 0) atomicExch(&g_cnt[b], 0);
}

extern "C" void kernel_launch(void* const* d_in, const int* in_sizes, int n_in,
                              void* d_out, int out_size)
{
    const float* target  = (const float*)d_in[0];  // [B, D]
    const float* context = (const float*)d_in[1];  // [B, S, D]
    const float* mask    = (const float*)d_in[2];  // [B, S]
    float* out = (float*)d_out;                    // [B, D]

    cudaFuncSetAttribute(attn_fused,
                         cudaFuncAttributeMaxDynamicSharedMemorySize,
                         SLOTS_BYTES);

    dim3 grid(B, NSPLIT);
    attn_fused<<<grid, THREADS, SLOTS_BYTES>>>(target, context, mask, out);
}

// round 14
// speedup vs baseline: 1.6144x; 1.0481x over previous
#include <cuda_runtime.h>
#include <math.h>

// Problem constants
#define B 32
#define S 2048
#define D 1024
#define MASK_PENALTY 100000000.0f

// Tiling
#define NSPLIT 16
#define WARPS 8
#define THREADS (WARPS * 32)                    // 256
#define ROWS_PER_SPLIT (S / NSPLIT)             // 128
#define NSLOTS 3                                // per-warp smem ring depth
#define ROW_BYTES (D * 4)                       // 4096

#define SLOTS_BYTES (WARPS * NSLOTS * ROW_BYTES)   // 96 KB dynamic smem

// Scratch (allocation-free: __device__ globals, zero-init)
__device__ float g_m[B * NSPLIT];
__device__ float g_l[B * NSPLIT];
__device__ __align__(16) float g_acc[(size_t)B * NSPLIT * D];  // 2 MB
__device__ int g_cnt[B];  // zero-init; self-resets each launch

// ---- mbarrier / bulk-copy helpers ----
__device__ __forceinline__ unsigned smem_u32(const void* p) {
    return (unsigned)__cvta_generic_to_shared(p);
}
__device__ __forceinline__ void mbar_init(unsigned mbar, unsigned count) {
    asm volatile("mbarrier.init.shared.b64 [%0], %1;" :: "r"(mbar), "r"(count)
                 : "memory");
}
__device__ __forceinline__ void mbar_expect_tx(unsigned mbar, unsigned bytes) {
    asm volatile("mbarrier.arrive.expect_tx.shared.b64 _, [%0], %1;"
                 :: "r"(mbar), "r"(bytes) : "memory");
}
__device__ __forceinline__ void mbar_wait(unsigned mbar, unsigned phase) {
    asm volatile(
        "{\n\t.reg .pred P;\n\t"
        "WL_%=:\n\t"
        "mbarrier.try_wait.parity.acquire.cta.shared::cta.b64 P, [%0], %1, 0x989680;\n\t"
        "@!P bra WL_%=;\n\t"
        "}" :: "r"(mbar), "r"(phase) : "memory");
}
__device__ __forceinline__ void bulk_cp_4k(unsigned dst, const void* src,
                                           unsigned mbar) {
    asm volatile(
        "cp.async.bulk.shared::cluster.global.mbarrier::complete_tx::bytes "
        "[%0], [%1], %2, [%3];"
        :: "r"(dst), "l"(src), "r"((unsigned)ROW_BYTES), "r"(mbar) : "memory");
}

// ---------------------------------------------------------------------------
// Fused single-pass online-softmax attention: mask skipping + compaction +
// per-warp cp.async.bulk smem ring, with PER-WARP CONTIGUOUS LIST CHUNKS.
// Each warp owns list entries [cnt*w/8, cnt*(w+1)/8): its in-order 3-deep
// bulk-copy pipeline issues strictly ASCENDING global addresses (~8KB steps)
// so every DRAM page region receives its requests consecutively
// (page-activation amortization), unlike the strided walk.
// Masked rows contribute exp(-1e8)==0.0f exactly in fp32 -> skipped.
// 8 warp partials merge in smem (ring reused) -> 1 per CTA -> last CTA per
// batch merges the NSPLIT split partials (no second kernel).
// ---------------------------------------------------------------------------
__global__ void __launch_bounds__(THREADS)
attn_fused(const float* __restrict__ target,
           const float* __restrict__ context,
           const float* __restrict__ mask,
           float* __restrict__ out)
{
    extern __shared__ __align__(128) char slots[];   // [WARPS][NSLOTS][4096]

    const int b     = blockIdx.x;
    const int split = blockIdx.y;
    const int w     = threadIdx.x >> 5;
    const int lane  = threadIdx.x & 31;
    const int s0    = split * ROWS_PER_SPLIT;

    __shared__ __align__(8) unsigned long long mbar_s[WARPS][NSLOTS];
    __shared__ short slist[ROWS_PER_SPLIT];
    __shared__ int   swcnt[4];
    __shared__ int   scnt;
    __shared__ float sm_[WARPS];
    __shared__ float sl_[WARPS];

    // ---- Barrier init + deterministic compaction of valid rows ----
    if (threadIdx.x < WARPS * NSLOTS)
        mbar_init(smem_u32(&mbar_s[threadIdx.x / NSLOTS][threadIdx.x % NSLOTS]), 1);

    const bool v = (threadIdx.x < ROWS_PER_SPLIT) &&
                   (mask[(size_t)b * S + s0 + threadIdx.x] != 0.f);
    const unsigned bal = __ballot_sync(0xffffffffu, v);
    if (lane == 0 && w < 4) swcnt[w] = __popc(bal);
    __syncthreads();

    if (threadIdx.x == 0) scnt = swcnt[0] + swcnt[1] + swcnt[2] + swcnt[3];
    if (v) {
        int off = 0;
#pragma unroll
        for (int i = 0; i < 4; i++) off += (i < w) ? swcnt[i] : 0;
        const int pos = off + __popc(bal & ((1u << lane) - 1u));
        slist[pos] = (short)threadIdx.x;
    }

    // Lane's slice of the query vector (registers)
    const float4* tg = (const float4*)(target + (size_t)b * D);
    float4 t[8];
#pragma unroll
    for (int i = 0; i < 8; i++) t[i] = tg[lane + 32 * i];

    __syncthreads();
    const int cnt = scnt;
    const float* cb = context + (size_t)b * S * D;

    // Per-warp CONTIGUOUS chunk of the compacted list (ascending addresses)
    const int begin = (cnt * w) / WARPS;
    const int end   = (cnt * (w + 1)) / WARPS;
    const int nrows = end - begin;

    // This warp's ring
    char* wslot = slots + (size_t)w * NSLOTS * ROW_BYTES;
    const unsigned slot_u32 = smem_u32(wslot);
    unsigned mb[NSLOTS];
#pragma unroll
    for (int k = 0; k < NSLOTS; k++) mb[k] = smem_u32(&mbar_s[w][k]);

    // Prologue: lane 0 issues bulk copies for the first NSLOTS rows (in order)
    if (lane == 0) {
#pragma unroll
        for (int k = 0; k < NSLOTS; k++) {
            if (k < nrows) {
                mbar_expect_tx(mb[k], ROW_BYTES);
                bulk_cp_4k(slot_u32 + k * ROW_BYTES,
                           cb + (size_t)(s0 + slist[begin + k]) * D, mb[k]);
            }
        }
    }

    float4 acc[8];
#pragma unroll
    for (int i = 0; i < 8; i++) acc[i] = make_float4(0.f, 0.f, 0.f, 0.f);

    float m = -INFINITY;
    float l = 0.f;

    // ---- Mainloop: consume rows from the smem ring (ascending order) ----
    for (int i = 0; i < nrows; i++) {
        const int slot  = i % NSLOTS;
        const unsigned phase = (unsigned)((i / NSLOTS) & 1);

        mbar_wait(mb[slot], phase);

        const float4* sp = (const float4*)(wslot + slot * ROW_BYTES);
        float4 c[8];
#pragma unroll
        for (int j = 0; j < 8; j++) c[j] = sp[lane + 32 * j];

        // Refill this slot with the row NSLOTS iterations ahead.
        const int nn = i + NSLOTS;
        if (lane == 0 && nn < nrows) {
            mbar_expect_tx(mb[slot], ROW_BYTES);
            bulk_cp_4k(slot_u32 + slot * ROW_BYTES,
                       cb + (size_t)(s0 + slist[begin + nn]) * D, mb[slot]);
        }

        // dot(context_row, target) for this lane's slice (2 chains)
        float d0 = 0.f, d1 = 0.f;
#pragma unroll
        for (int j = 0; j < 8; j++) {
            d0 = fmaf(c[j].x, t[j].x, d0);
            d1 = fmaf(c[j].y, t[j].y, d1);
            d0 = fmaf(c[j].z, t[j].z, d0);
            d1 = fmaf(c[j].w, t[j].w, d1);
        }
        float dot = d0 + d1;
#pragma unroll
        for (int off = 16; off > 0; off >>= 1)
            dot += __shfl_xor_sync(0xffffffffu, dot, off);

        // online softmax update (valid row => mask penalty term is 0)
        const float mnew  = fmaxf(m, dot);
        const float scale = __expf(m - mnew);     // 0 on first valid row
        const float wgt   = __expf(dot - mnew);
        l = l * scale + wgt;
#pragma unroll
        for (int j = 0; j < 8; j++) {
            acc[j].x = fmaf(acc[j].x, scale, wgt * c[j].x);
            acc[j].y = fmaf(acc[j].y, scale, wgt * c[j].y);
            acc[j].z = fmaf(acc[j].z, scale, wgt * c[j].z);
            acc[j].w = fmaf(acc[j].w, scale, wgt * c[j].w);
        }
        m = mnew;
    }

    // ---- In-CTA merge of the 8 warp partials (ring memory reused) ----
    if (lane == 0) { sm_[w] = m; sl_[w] = l; }
    __syncthreads();   // all warps done with their ring slots

    float Mcta = -INFINITY;
#pragma unroll
    for (int i = 0; i < WARPS; i++) Mcta = fmaxf(Mcta, sm_[i]);

    float4* sacc = (float4*)slots;   // [WARPS][D/4] = 32 KB within 96 KB
    const float f = (m > -INFINITY) ? __expf(m - Mcta) : 0.f;
#pragma unroll
    for (int i = 0; i < 8; i++) {
        float4 a = acc[i];
        a.x *= f; a.y *= f; a.z *= f; a.w *= f;
        sacc[w * (D / 4) + lane + 32 * i] = a;
    }
    __syncthreads();

    // 256 threads sum across the 8 warps, write CTA partial
    const int pidx = b * NSPLIT + split;
    const int d4 = threadIdx.x;
    float4 sum = sacc[d4];
#pragma unroll
    for (int i = 1; i < WARPS; i++) {
        const float4 vv = sacc[i * (D / 4) + d4];
        sum.x += vv.x; sum.y += vv.y; sum.z += vv.z; sum.w += vv.w;
    }
    ((float4*)(g_acc + (size_t)pidx * D))[d4] = sum;

    if (threadIdx.x == 0) {
        float L = 0.f;
#pragma unroll
        for (int i = 0; i < WARPS; i++)
            L += (sm_[i] > -INFINITY ? __expf(sm_[i] - Mcta) : 0.f) * sl_[i];
        g_m[pidx] = Mcta;   // -inf if the whole split is masked
        g_l[pidx] = L;
    }

    // ---- Last CTA per batch merges the NSPLIT partials ----
    __threadfence();
    __syncthreads();
    __shared__ int isLast;
    if (threadIdx.x == 0)
        isLast = (atomicAdd(&g_cnt[b], 1) == NSPLIT - 1);
    __syncthreads();
    if (!isLast) return;
    __threadfence();  // acquire

    float pm[NSPLIT], pl[NSPLIT];
#pragma unroll
    for (int p = 0; p < NSPLIT; p++) {
        pm[p] = __ldcg(&g_m[b * NSPLIT + p]);
        pl[p] = __ldcg(&g_l[b * NSPLIT + p]);
    }
    // M is finite: position 0 of every batch is guaranteed valid.
    float M = -INFINITY;
#pragma unroll
    for (int p = 0; p < NSPLIT; p++) M = fmaxf(M, pm[p]);
    float L = 0.f;
#pragma unroll
    for (int p = 0; p < NSPLIT; p++)
        L += (pm[p] > -INFINITY ? __expf(pm[p] - M) : 0.f) * pl[p];
    const float Linv = 1.f / L;

    float4 a = make_float4(0.f, 0.f, 0.f, 0.f);
#pragma unroll
    for (int p = 0; p < NSPLIT; p++) {
        const float fp = (pm[p] > -INFINITY) ? __expf(pm[p] - M) : 0.f;
        const float4 vv =
            __ldcg((const float4*)(g_acc + (size_t)(b * NSPLIT + p) * D) + d4);
        a.x = fmaf(fp, vv.x, a.x);
        a.y = fmaf(fp, vv.y, a.y);
        a.z = fmaf(fp, vv.z, a.z);
        a.w = fmaf(fp, vv.w, a.w);
    }
    a.x *= Linv; a.y *= Linv; a.z *= Linv; a.w *= Linv;
    ((float4*)(out + (size_t)b * D))[d4] = a;

    if (threadIdx.x == 0) atomicExch(&g_cnt[b], 0);
}

extern "C" void kernel_launch(void* const* d_in, const int* in_sizes, int n_in,
                              void* d_out, int out_size)
{
    const float* target  = (const float*)d_in[0];  // [B, D]
    const float* context = (const float*)d_in[1];  // [B, S, D]
    const float* mask    = (const float*)d_in[2];  // [B, S]
    float* out = (float*)d_out;                    // [B, D]

    cudaFuncSetAttribute(attn_fused,
                         cudaFuncAttributeMaxDynamicSharedMemorySize,
                         SLOTS_BYTES);

    dim3 grid(B, NSPLIT);
    attn_fused<<<grid, THREADS, SLOTS_BYTES>>>(target, context, mask, out);
}